// round 16
// baseline (speedup 1.0000x reference)
#include <cuda_runtime.h>
#include <cuda_fp16.h>
#include <cstdint>

#define Bz 16
#define Nn 1024
#define Cc 768
#define Dd 384

#define TILE_B  16384            // 128 rows x 128B (64 fp16 k-elems per row)
#define STAGE_B 32768            // A tile + B tile
#define NSTAGE  3
#define SMEM_DYN (NSTAGE*STAGE_B + 128)

// ---------------- static scratch (plain fp16, LD = K) ----------------
__device__ __align__(16) __half g_xh [(size_t)Bz*Nn*Cc];     // A in proj
__device__ __align__(16) __half g_wh [(size_t)3*Dd*Cc];      // B in proj (row n, col k)
__device__              float   g_bias[3*Dd];
__device__ __align__(16) __half g_th [(size_t)Bz*Nn*Dd];     // A in score
__device__ __align__(16) __half g_ph [(size_t)Bz*Nn*Dd];     // B in score
__device__ __align__(16) __half g_gh [(size_t)Bz*Dd*Nn];     // B in av (row d, col token)
__device__ __align__(16) float  g_attn[(size_t)Bz*Nn*Nn];
__device__ __align__(16) __half g_ath[(size_t)Bz*Nn*Nn];     // A in av (softmax rows)
__device__ __align__(16) __half g_odh[(size_t)Bz*Nn*Dd];     // A in out
__device__ __align__(16) __half g_woh[(size_t)Cc*Dd];        // B in out

// ---------------- helpers ----------------
__device__ __forceinline__ uint32_t smem_u32(const void* p){
    uint32_t a;
    asm("{ .reg .u64 t; cvta.to.shared.u64 t, %1; cvt.u32.u64 %0, t; }" : "=r"(a) : "l"(p));
    return a;
}
__device__ __forceinline__ void cpa16(uint32_t dst, const void* src){
    asm volatile("cp.async.cg.shared.global [%0], [%1], 16;" :: "r"(dst), "l"(src));
}
#define CP_COMMIT() asm volatile("cp.async.commit_group;" ::: "memory")
#define CP_WAIT(N)  asm volatile("cp.async.wait_group %0;" :: "n"(N) : "memory")

__device__ __forceinline__ void ldsm4(uint32_t (&d)[4], uint32_t a){
    asm volatile("ldmatrix.sync.aligned.m8n8.x4.shared.b16 {%0,%1,%2,%3}, [%4];"
        : "=r"(d[0]), "=r"(d[1]), "=r"(d[2]), "=r"(d[3]) : "r"(a));
}
__device__ __forceinline__ void mma16816(float (&c)[4], const uint32_t (&a)[4],
                                         uint32_t b0, uint32_t b1){
    asm volatile("mma.sync.aligned.m16n8k16.row.col.f32.f16.f16.f32 "
        "{%0,%1,%2,%3}, {%4,%5,%6,%7}, {%8,%9}, {%0,%1,%2,%3};"
        : "+f"(c[0]), "+f"(c[1]), "+f"(c[2]), "+f"(c[3])
        : "r"(a[0]), "r"(a[1]), "r"(a[2]), "r"(a[3]), "r"(b0), "r"(b1));
}

__device__ __forceinline__ uint32_t h2u2(__half a, __half b){
    return (uint32_t)__half_as_ushort(a) | ((uint32_t)__half_as_ushort(b) << 16);
}

// ---------------- pure fp16 HMMA GEMM core ----------------
// Chunk = 64 k (128B rows). CTA tile 128x128, 8 warps (2x4), warp tile 64x32.
// B fragments via 2x ldsm4 per ks (validated R10/R14).
__device__ __forceinline__ void gemm1(
    const __half* __restrict__ A, int ldA,
    const __half* __restrict__ B, int ldB,
    int nkb, char* sm, float acc[4][4][4])
{
    const int tid  = threadIdx.x;
    const int lane = tid & 31;
    const int w    = tid >> 5;
    const int wr   = w >> 2, wc = w & 3;
    const uint32_t sbase = (smem_u32(sm) + 127u) & ~127u;

    int goA[4], goB[4], smo[4];
#pragma unroll
    for (int i = 0; i < 4; i++){
        int idx = i * 256 + tid;
        int rr = idx >> 3, cc = idx & 7;
        goA[i] = rr * ldA + cc * 8;
        goB[i] = rr * ldB + cc * 8;
        smo[i] = rr * 128 + ((cc * 16) ^ ((rr & 7) << 4));
    }

    const int xorv = (lane & 7) << 4;
    int arow[4];
#pragma unroll
    for (int mi = 0; mi < 4; mi++) arow[mi] = (wr * 64 + mi * 16 + (lane & 15)) * 128;
    const int brow4 = (wc * 32 + ((lane >> 4) << 3) + (lane & 7)) * 128;
    const int acs = (lane & 16);
    const int bcs = (lane & 8) << 1;

#pragma unroll
    for (int mi = 0; mi < 4; mi++)
#pragma unroll
        for (int ni = 0; ni < 4; ni++)
#pragma unroll
            for (int q = 0; q < 4; q++) acc[mi][ni][q] = 0.f;

    // prologue: issue chunks 0,1
#pragma unroll
    for (int pc = 0; pc < 2; pc++){
        const uint32_t s = sbase + pc * STAGE_B;
        const __half* Ak = A + pc * 64;
        const __half* Bk = B + pc * 64;
#pragma unroll
        for (int i = 0; i < 4; i++) cpa16(s + smo[i], Ak + goA[i]);
#pragma unroll
        for (int i = 0; i < 4; i++) cpa16(s + TILE_B + smo[i], Bk + goB[i]);
        CP_COMMIT();
    }

    int stg = 0;
    for (int c = 0; c < nkb; ++c){
        if (c + 1 < nkb) { CP_WAIT(1); } else { CP_WAIT(0); }
        __syncthreads();

        const uint32_t sA = sbase + stg * STAGE_B;
        const uint32_t sB = sA + TILE_B;
#pragma unroll
        for (int ks = 0; ks < 4; ks++){
            const int chA = ((ks << 5) | acs);
            const int chB = ((ks << 5) | bcs);
            uint32_t ahi[4][4], bh[2][4];
#pragma unroll
            for (int p = 0; p < 2; p++)
                ldsm4(bh[p], sB + brow4 + p * 2048 + (chB ^ xorv));
#pragma unroll
            for (int mi = 0; mi < 4; mi++)
                ldsm4(ahi[mi], sA + arow[mi] + (chA ^ xorv));
#pragma unroll
            for (int ni = 0; ni < 4; ni++)
#pragma unroll
                for (int mi = 0; mi < 4; mi++)
                    mma16816(acc[mi][ni], ahi[mi],
                             bh[ni >> 1][(ni & 1) * 2], bh[ni >> 1][(ni & 1) * 2 + 1]);
        }

        // issue chunk c+2 into the stage consumed at c-1 (safe: barrier above)
        if (c + 2 < nkb){
            const int ns = (stg + 2 >= NSTAGE) ? stg + 2 - NSTAGE : stg + 2;
            const uint32_t s = sbase + ns * STAGE_B;
            const __half* Ak = A + (c + 2) * 64;
            const __half* Bk = B + (c + 2) * 64;
#pragma unroll
            for (int i = 0; i < 4; i++) cpa16(s + smo[i], Ak + goA[i]);
#pragma unroll
            for (int i = 0; i < 4; i++) cpa16(s + TILE_B + smo[i], Bk + goB[i]);
            CP_COMMIT();
        }
        stg = (stg + 1 == NSTAGE) ? 0 : stg + 1;
    }
}

// ---------------- merged conversion kernel ----------------
#define CVT_XB 12288
#define CVT_WB 864
#define CVT_OB 288
__global__ __launch_bounds__(256) void k_cvt_all(
    const float* __restrict__ x,
    const float* __restrict__ Wt, const float* __restrict__ bt,
    const float* __restrict__ Wp, const float* __restrict__ bp,
    const float* __restrict__ Wg, const float* __restrict__ bg,
    const float* __restrict__ Wo)
{
    const int blk = blockIdx.x;
    if (blk < CVT_XB){
        const int idx = blk * 256 + threadIdx.x;
        const int m = idx / 192, kq = idx % 192;
        const int k = kq * 4;
        float4 v = *(const float4*)(x + (size_t)m * Cc + k);
        uint2 u;
        u.x = h2u2(__float2half_rn(v.x), __float2half_rn(v.y));
        u.y = h2u2(__float2half_rn(v.z), __float2half_rn(v.w));
        *(uint2*)(g_xh + (size_t)m * Cc + k) = u;
    } else if (blk < CVT_XB + CVT_WB){
        const int idx = (blk - CVT_XB) * 256 + threadIdx.x;
        const int n = idx / 192, kq = idx % 192;
        const int which = n / Dd, d = n % Dd;
        const int k = kq * 4;
        const float* W = (which == 0) ? Wt : (which == 1) ? Wp : Wg;
        __half h[4];
#pragma unroll
        for (int t = 0; t < 4; t++)
            h[t] = __float2half_rn(W[(size_t)(k + t) * Dd + d]);
        uint2 u; u.x = h2u2(h[0], h[1]); u.y = h2u2(h[2], h[3]);
        *(uint2*)(g_wh + (size_t)n * Cc + k) = u;
        if (kq == 0){
            const float* bb = (which == 0) ? bt : (which == 1) ? bp : bg;
            g_bias[n] = bb[d];
        }
    } else {
        const int idx = (blk - CVT_XB - CVT_WB) * 256 + threadIdx.x;
        const int n = idx / 96, kq = idx % 96;
        const int k = kq * 4;
        __half h[4];
#pragma unroll
        for (int t = 0; t < 4; t++)
            h[t] = __float2half_rn(Wo[(size_t)(k + t) * Cc + n]);
        uint2 u; u.x = h2u2(h[0], h[1]); u.y = h2u2(h[2], h[3]);
        *(uint2*)(g_woh + (size_t)n * Dd + k) = u;
    }
}

// ---------------- GEMM 1: projections ----------------
// seg 0/1: direct coalesced stores. seg 2 (g): transpose via smem bounce,
// then fully-coalesced 128B-per-thread row writes (replaces 2B scatter).
#define TS_LD 136   // halves per transposed smem row (128 + 8 pad)
__global__ __launch_bounds__(256, 2) void k_proj_t(){
    extern __shared__ char sm[];
    const int lane = threadIdx.x & 31, w = threadIdx.x >> 5;
    const int wr = w >> 2, wc = w & 3;
    const int n0 = blockIdx.x * 128, m0 = blockIdx.y * 128;
    float acc[4][4][4];
    gemm1(g_xh + (size_t)m0 * Cc, Cc,
          g_wh + (size_t)n0 * Cc, Cc, Cc / 64, sm, acc);

    const int seg = n0 / Dd, d0 = n0 % Dd;
    if (seg != 2){
#pragma unroll
        for (int mi = 0; mi < 4; mi++)
#pragma unroll
        for (int ni = 0; ni < 4; ni++)
#pragma unroll
        for (int h = 0; h < 2; h++){
            const int r   = wr * 64 + mi * 16 + (lane >> 2) + h * 8;
            const int col = wc * 32 + ni * 8 + (lane & 3) * 2;
            const int mrow = m0 + r;
            const int ng = n0 + col;
            const float v0 = acc[mi][ni][h * 2]     + g_bias[ng];
            const float v1 = acc[mi][ni][h * 2 + 1] + g_bias[ng + 1];
            const uint32_t u = h2u2(__float2half_rn(v0), __float2half_rn(v1));
            const int d = d0 + col;
            if (seg == 0) *(uint32_t*)(g_th + (size_t)mrow * Dd + d) = u;
            else          *(uint32_t*)(g_ph + (size_t)mrow * Dd + d) = u;
        }
    } else {
        // stage transposed tile in smem: ts[col][row], row-contiguous
        __half* ts = (__half*)sm;
        __syncthreads();   // pipeline smem now dead for all warps
#pragma unroll
        for (int mi = 0; mi < 4; mi++)
#pragma unroll
        for (int ni = 0; ni < 4; ni++)
#pragma unroll
        for (int h = 0; h < 2; h++){
            const int r   = wr * 64 + mi * 16 + (lane >> 2) + h * 8;
            const int col = wc * 32 + ni * 8 + (lane & 3) * 2;
            const int ng = n0 + col;
            ts[(col)     * TS_LD + r] = __float2half_rn(acc[mi][ni][h * 2]     + g_bias[ng]);
            ts[(col + 1) * TS_LD + r] = __float2half_rn(acc[mi][ni][h * 2 + 1] + g_bias[ng + 1]);
        }
        __syncthreads();
        // coalesced write-out: thread t -> d = t>>1, half = t&1 (64 tokens = 8 uint4)
        const int d    = threadIdx.x >> 1;
        const int half = threadIdx.x & 1;
        const int b    = m0 >> 10;
        const int ml0  = (m0 & 1023) + half * 64;
        const __half* src = ts + d * TS_LD + half * 64;
        __half* dst = g_gh + (size_t)(b * Dd + d0 + d) * Nn + ml0;
#pragma unroll
        for (int q = 0; q < 8; q++)
            ((uint4*)dst)[q] = ((const uint4*)src)[q];
    }
}

// ---------------- GEMM 2: scores = (theta @ phi^T) * adj ----------------
__global__ __launch_bounds__(256, 2) void k_score_t(const float* __restrict__ adj){
    extern __shared__ char sm[];
    const int lane = threadIdx.x & 31, w = threadIdx.x >> 5;
    const int wr = w >> 2, wc = w & 3;
    const int b = blockIdx.z, j0 = blockIdx.x * 128, i0 = blockIdx.y * 128;
    float acc[4][4][4];
    gemm1(g_th + (size_t)(b * Nn + i0) * Dd, Dd,
          g_ph + (size_t)(b * Nn + j0) * Dd, Dd, Dd / 64, sm, acc);

#pragma unroll
    for (int mi = 0; mi < 4; mi++)
#pragma unroll
    for (int ni = 0; ni < 4; ni++)
#pragma unroll
    for (int h = 0; h < 2; h++){
        const int i = i0 + wr * 64 + mi * 16 + (lane >> 2) + h * 8;
        const int j = j0 + wc * 32 + ni * 8 + (lane & 3) * 2;
        const size_t idx = ((size_t)b * Nn + i) * Nn + j;
        const float2 a2 = *(const float2*)(adj + idx);
        float2 o;
        o.x = acc[mi][ni][h * 2]     * a2.x;
        o.y = acc[mi][ni][h * 2 + 1] * a2.y;
        *(float2*)(g_attn + idx) = o;
    }
}

// ---------------- softmax -> plain fp16 rows ----------------
// 4 rows per 256-thread block; 64 threads per row; 4 float4 per thread (MLP=4).
__global__ __launch_bounds__(256) void k_softmax2(){
    const int slot = threadIdx.x >> 6;
    const int t    = threadIdx.x & 63;
    const size_t row = (size_t)blockIdx.x * 4 + slot;
    const float4* p = (const float4*)(g_attn + row * Nn);

    float4 v[4];
#pragma unroll
    for (int q = 0; q < 4; q++) v[q] = p[t + q * 64];

    float m = -1e30f;
#pragma unroll
    for (int q = 0; q < 4; q++)
        m = fmaxf(m, fmaxf(fmaxf(v[q].x, v[q].y), fmaxf(v[q].z, v[q].w)));
#pragma unroll
    for (int o = 16; o; o >>= 1) m = fmaxf(m, __shfl_xor_sync(0xffffffffu, m, o));
    __shared__ float red[8];
    const int wid = threadIdx.x >> 5;
    if ((threadIdx.x & 31) == 0) red[wid] = m;
    __syncthreads();
    const float bm = fmaxf(red[slot * 2], red[slot * 2 + 1]);
    __syncthreads();

    float s = 0.f;
#pragma unroll
    for (int q = 0; q < 4; q++){
        v[q].x = __expf(v[q].x - bm); v[q].y = __expf(v[q].y - bm);
        v[q].z = __expf(v[q].z - bm); v[q].w = __expf(v[q].w - bm);
        s += (v[q].x + v[q].y) + (v[q].z + v[q].w);
    }
#pragma unroll
    for (int o = 16; o; o >>= 1) s += __shfl_xor_sync(0xffffffffu, s, o);
    if ((threadIdx.x & 31) == 0) red[wid] = s;
    __syncthreads();
    const float inv = 1.0f / (red[slot * 2] + red[slot * 2 + 1]);

    __half* dst = g_ath + row * Nn;
#pragma unroll
    for (int q = 0; q < 4; q++){
        uint2 u;
        u.x = h2u2(__float2half_rn(v[q].x * inv), __float2half_rn(v[q].y * inv));
        u.y = h2u2(__float2half_rn(v[q].z * inv), __float2half_rn(v[q].w * inv));
        *(uint2*)(dst + (t + q * 64) * 4) = u;
    }
}

// ---------------- GEMM 3: attn @ g ----------------
__global__ __launch_bounds__(256, 2) void k_av_t(){
    extern __shared__ char sm[];
    const int lane = threadIdx.x & 31, w = threadIdx.x >> 5;
    const int wr = w >> 2, wc = w & 3;
    const int b = blockIdx.z, n0 = blockIdx.x * 128, i0 = blockIdx.y * 128;
    float acc[4][4][4];
    gemm1(g_ath + (size_t)(b * Nn + i0) * Nn, Nn,
          g_gh  + (size_t)(b * Dd + n0) * Nn, Nn, Nn / 64, sm, acc);

#pragma unroll
    for (int mi = 0; mi < 4; mi++)
#pragma unroll
    for (int ni = 0; ni < 4; ni++)
#pragma unroll
    for (int h = 0; h < 2; h++){
        const int r   = wr * 64 + mi * 16 + (lane >> 2) + h * 8;
        const int col = wc * 32 + ni * 8 + (lane & 3) * 2;
        const int mrow = b * Nn + i0 + r;
        const __half h0 = __float2half_rn(acc[mi][ni][h * 2]);
        const __half h1 = __float2half_rn(acc[mi][ni][h * 2 + 1]);
        *(uint32_t*)(g_odh + (size_t)mrow * Dd + n0 + col) = h2u2(h0, h1);
    }
}

// ---------------- GEMM 4: output + bias + residual ----------------
__global__ __launch_bounds__(256, 2) void k_out_t(
    const float* __restrict__ x, const float* __restrict__ bo, float* __restrict__ out)
{
    extern __shared__ char sm[];
    const int lane = threadIdx.x & 31, w = threadIdx.x >> 5;
    const int wr = w >> 2, wc = w & 3;
    const int n0 = blockIdx.x * 128, m0 = blockIdx.y * 128;
    float acc[4][4][4];
    gemm1(g_odh + (size_t)m0 * Dd, Dd,
          g_woh + (size_t)n0 * Dd, Dd, Dd / 64, sm, acc);

#pragma unroll
    for (int mi = 0; mi < 4; mi++)
#pragma unroll
    for (int ni = 0; ni < 4; ni++)
#pragma unroll
    for (int h = 0; h < 2; h++){
        const int row = m0 + wr * 64 + mi * 16 + (lane >> 2) + h * 8;
        const int cg  = n0 + wc * 32 + ni * 8 + (lane & 3) * 2;
        const size_t idx = (size_t)row * Cc + cg;
        const float2 xv = *(const float2*)(x + idx);
        const float2 bv = *(const float2*)(bo + cg);
        float2 o;
        o.x = acc[mi][ni][h * 2]     + bv.x + xv.x;
        o.y = acc[mi][ni][h * 2 + 1] + bv.y + xv.y;
        *(float2*)(out + idx) = o;
    }
}

// ---------------------------------------------------------------------------
extern "C" void kernel_launch(void* const* d_in, const int* in_sizes, int n_in,
                              void* d_out, int out_size)
{
    const float* x  = (const float*)d_in[0];
    const float* adj = (const float*)d_in[1];
    const float* Wt = (const float*)d_in[2];
    const float* bt = (const float*)d_in[3];
    const float* Wp = (const float*)d_in[4];
    const float* bp = (const float*)d_in[5];
    const float* Wg = (const float*)d_in[6];
    const float* bg = (const float*)d_in[7];
    const float* Wo = (const float*)d_in[8];
    const float* bo = (const float*)d_in[9];
    float* out = (float*)d_out;

    static bool attr_done = false;
    if (!attr_done){
        cudaFuncSetAttribute(k_proj_t,  cudaFuncAttributeMaxDynamicSharedMemorySize, SMEM_DYN);
        cudaFuncSetAttribute(k_score_t, cudaFuncAttributeMaxDynamicSharedMemorySize, SMEM_DYN);
        cudaFuncSetAttribute(k_av_t,    cudaFuncAttributeMaxDynamicSharedMemorySize, SMEM_DYN);
        cudaFuncSetAttribute(k_out_t,   cudaFuncAttributeMaxDynamicSharedMemorySize, SMEM_DYN);
        attr_done = true;
    }

    k_cvt_all<<<CVT_XB + CVT_WB + CVT_OB, 256>>>(x, Wt, bt, Wp, bp, Wg, bg, Wo);

    k_proj_t <<<dim3(9, 128),   256, SMEM_DYN>>>();
    k_score_t<<<dim3(8, 8, Bz), 256, SMEM_DYN>>>(adj);
    k_softmax2<<<(Bz * Nn) / 4, 256>>>();
    k_av_t   <<<dim3(3, 8, Bz), 256, SMEM_DYN>>>();
    k_out_t  <<<dim3(6, 128),   256, SMEM_DYN>>>(x, bo, out);
}

// round 17
// speedup vs baseline: 1.0113x; 1.0113x over previous
#include <cuda_runtime.h>
#include <cuda_fp16.h>
#include <cstdint>

#define Bz 16
#define Nn 1024
#define Cc 768
#define Dd 384

#define TILE_B  16384            // 128 rows x 128B (64 fp16 k-elems per row)
#define STAGE_B 32768            // A tile + B tile
#define NSTAGE  3
#define SMEM_DYN (NSTAGE*STAGE_B + 128)

// ---------------- static scratch (plain fp16, LD = K) ----------------
__device__ __align__(16) __half g_xh [(size_t)Bz*Nn*Cc];     // A in proj
__device__ __align__(16) __half g_wh [(size_t)3*Dd*Cc];      // B in proj (row n, col k)
__device__              float   g_bias[3*Dd];
__device__ __align__(16) __half g_th [(size_t)Bz*Nn*Dd];     // A in score
__device__ __align__(16) __half g_ph [(size_t)Bz*Nn*Dd];     // B in score
__device__ __align__(16) __half g_gh [(size_t)Bz*Dd*Nn];     // B in av (row d, col token)
__device__ __align__(16) float  g_attn[(size_t)Bz*Nn*Nn];
__device__ __align__(16) __half g_ath[(size_t)Bz*Nn*Nn];     // A in av (softmax rows)
__device__ __align__(16) __half g_odh[(size_t)Bz*Nn*Dd];     // A in out
__device__ __align__(16) __half g_woh[(size_t)Cc*Dd];        // B in out

// ---------------- helpers ----------------
__device__ __forceinline__ uint32_t smem_u32(const void* p){
    uint32_t a;
    asm("{ .reg .u64 t; cvta.to.shared.u64 t, %1; cvt.u32.u64 %0, t; }" : "=r"(a) : "l"(p));
    return a;
}
__device__ __forceinline__ void cpa16(uint32_t dst, const void* src){
    asm volatile("cp.async.cg.shared.global [%0], [%1], 16;" :: "r"(dst), "l"(src));
}
#define CP_COMMIT() asm volatile("cp.async.commit_group;" ::: "memory")
#define CP_WAIT(N)  asm volatile("cp.async.wait_group %0;" :: "n"(N) : "memory")

__device__ __forceinline__ void ldsm4(uint32_t (&d)[4], uint32_t a){
    asm volatile("ldmatrix.sync.aligned.m8n8.x4.shared.b16 {%0,%1,%2,%3}, [%4];"
        : "=r"(d[0]), "=r"(d[1]), "=r"(d[2]), "=r"(d[3]) : "r"(a));
}
__device__ __forceinline__ void mma16816(float (&c)[4], const uint32_t (&a)[4],
                                         uint32_t b0, uint32_t b1){
    asm volatile("mma.sync.aligned.m16n8k16.row.col.f32.f16.f16.f32 "
        "{%0,%1,%2,%3}, {%4,%5,%6,%7}, {%8,%9}, {%0,%1,%2,%3};"
        : "+f"(c[0]), "+f"(c[1]), "+f"(c[2]), "+f"(c[3])
        : "r"(a[0]), "r"(a[1]), "r"(a[2]), "r"(a[3]), "r"(b0), "r"(b1));
}

__device__ __forceinline__ uint32_t h2u2(__half a, __half b){
    return (uint32_t)__half_as_ushort(a) | ((uint32_t)__half_as_ushort(b) << 16);
}

// ---------------- pure fp16 HMMA GEMM core ----------------
// Chunk = 64 k (128B rows). CTA tile 128x128, 4 warps (2x2), warp tile 64x64.
// 128 threads/CTA, 2 CTAs/SM. Halves ldsm bytes per MMA vs 8-warp version.
__device__ __forceinline__ void gemm1(
    const __half* __restrict__ A, int ldA,
    const __half* __restrict__ B, int ldB,
    int nkb, char* sm, float acc[4][8][4])
{
    const int tid  = threadIdx.x;          // 0..127
    const int lane = tid & 31;
    const int w    = tid >> 5;             // 0..3
    const int wr   = w >> 1, wc = w & 1;
    const uint32_t sbase = (smem_u32(sm) + 127u) & ~127u;

    // gmem->smem loader: thread covers rows t8 + i*16 (i<8), 16B at col c8.
    // i*16 rows preserves the (row&7) swizzle term, so one base + strides.
    const int t8 = tid >> 3, c8 = tid & 7;
    const int goA0 = t8 * ldA + c8 * 8;
    const int goB0 = t8 * ldB + c8 * 8;
    const int smo0 = t8 * 128 + ((c8 * 16) ^ ((t8 & 7) << 4));

    const int xorv = (lane & 7) << 4;
    int arow[4];
#pragma unroll
    for (int mi = 0; mi < 4; mi++) arow[mi] = (wr * 64 + mi * 16 + (lane & 15)) * 128;
    // B ldsm4 lane map: 16 rows (2 n8-blocks) x 2 k-halves per ldsm4; p<4 covers 64 rows
    const int brow4 = (wc * 64 + ((lane >> 4) << 3) + (lane & 7)) * 128;
    const int acs = (lane & 16);
    const int bcs = (lane & 8) << 1;

#pragma unroll
    for (int mi = 0; mi < 4; mi++)
#pragma unroll
        for (int ni = 0; ni < 8; ni++)
#pragma unroll
            for (int q = 0; q < 4; q++) acc[mi][ni][q] = 0.f;

    // prologue: issue chunks 0,1
#pragma unroll
    for (int pc = 0; pc < 2; pc++){
        const uint32_t s = sbase + pc * STAGE_B;
        const __half* Ak = A + pc * 64;
        const __half* Bk = B + pc * 64;
#pragma unroll
        for (int i = 0; i < 8; i++) cpa16(s + smo0 + i * 2048, Ak + goA0 + i * 16 * ldA);
#pragma unroll
        for (int i = 0; i < 8; i++) cpa16(s + TILE_B + smo0 + i * 2048, Bk + goB0 + i * 16 * ldB);
        CP_COMMIT();
    }

    int stg = 0;
    for (int c = 0; c < nkb; ++c){
        if (c + 1 < nkb) { CP_WAIT(1); } else { CP_WAIT(0); }
        __syncthreads();

        const uint32_t sA = sbase + stg * STAGE_B;
        const uint32_t sB = sA + TILE_B;
#pragma unroll
        for (int ks = 0; ks < 4; ks++){
            const int chA = ((ks << 5) | acs);
            const int chB = ((ks << 5) | bcs);
            uint32_t ahi[4][4], bh[4][4];
#pragma unroll
            for (int p = 0; p < 4; p++)
                ldsm4(bh[p], sB + brow4 + p * 2048 + (chB ^ xorv));
#pragma unroll
            for (int mi = 0; mi < 4; mi++)
                ldsm4(ahi[mi], sA + arow[mi] + (chA ^ xorv));
#pragma unroll
            for (int ni = 0; ni < 8; ni++)
#pragma unroll
                for (int mi = 0; mi < 4; mi++)
                    mma16816(acc[mi][ni], ahi[mi],
                             bh[ni >> 1][(ni & 1) * 2], bh[ni >> 1][(ni & 1) * 2 + 1]);
        }

        // issue chunk c+2 into the stage consumed at c-1 (safe: barrier above)
        if (c + 2 < nkb){
            const int ns = (stg + 2 >= NSTAGE) ? stg + 2 - NSTAGE : stg + 2;
            const uint32_t s = sbase + ns * STAGE_B;
            const __half* Ak = A + (c + 2) * 64;
            const __half* Bk = B + (c + 2) * 64;
#pragma unroll
            for (int i = 0; i < 8; i++) cpa16(s + smo0 + i * 2048, Ak + goA0 + i * 16 * ldA);
#pragma unroll
            for (int i = 0; i < 8; i++) cpa16(s + TILE_B + smo0 + i * 2048, Bk + goB0 + i * 16 * ldB);
            CP_COMMIT();
        }
        stg = (stg + 1 == NSTAGE) ? 0 : stg + 1;
    }
}

// ---------------- merged conversion kernel ----------------
#define CVT_XB 12288
#define CVT_WB 864
#define CVT_OB 288
__global__ __launch_bounds__(256) void k_cvt_all(
    const float* __restrict__ x,
    const float* __restrict__ Wt, const float* __restrict__ bt,
    const float* __restrict__ Wp, const float* __restrict__ bp,
    const float* __restrict__ Wg, const float* __restrict__ bg,
    const float* __restrict__ Wo)
{
    const int blk = blockIdx.x;
    if (blk < CVT_XB){
        const int idx = blk * 256 + threadIdx.x;
        const int m = idx / 192, kq = idx % 192;
        const int k = kq * 4;
        float4 v = *(const float4*)(x + (size_t)m * Cc + k);
        uint2 u;
        u.x = h2u2(__float2half_rn(v.x), __float2half_rn(v.y));
        u.y = h2u2(__float2half_rn(v.z), __float2half_rn(v.w));
        *(uint2*)(g_xh + (size_t)m * Cc + k) = u;
    } else if (blk < CVT_XB + CVT_WB){
        const int idx = (blk - CVT_XB) * 256 + threadIdx.x;
        const int n = idx / 192, kq = idx % 192;
        const int which = n / Dd, d = n % Dd;
        const int k = kq * 4;
        const float* W = (which == 0) ? Wt : (which == 1) ? Wp : Wg;
        __half h[4];
#pragma unroll
        for (int t = 0; t < 4; t++)
            h[t] = __float2half_rn(W[(size_t)(k + t) * Dd + d]);
        uint2 u; u.x = h2u2(h[0], h[1]); u.y = h2u2(h[2], h[3]);
        *(uint2*)(g_wh + (size_t)n * Cc + k) = u;
        if (kq == 0){
            const float* bb = (which == 0) ? bt : (which == 1) ? bp : bg;
            g_bias[n] = bb[d];
        }
    } else {
        const int idx = (blk - CVT_XB - CVT_WB) * 256 + threadIdx.x;
        const int n = idx / 96, kq = idx % 96;
        const int k = kq * 4;
        __half h[4];
#pragma unroll
        for (int t = 0; t < 4; t++)
            h[t] = __float2half_rn(Wo[(size_t)(k + t) * Cc + n]);
        uint2 u; u.x = h2u2(h[0], h[1]); u.y = h2u2(h[2], h[3]);
        *(uint2*)(g_woh + (size_t)n * Dd + k) = u;
    }
}

// ---------------- GEMM 1: projections ----------------
__global__ __launch_bounds__(128, 2) void k_proj_t(){
    extern __shared__ char sm[];
    const int lane = threadIdx.x & 31, w = threadIdx.x >> 5;
    const int wr = w >> 1, wc = w & 1;
    const int n0 = blockIdx.x * 128, m0 = blockIdx.y * 128;
    float acc[4][8][4];
    gemm1(g_xh + (size_t)m0 * Cc, Cc,
          g_wh + (size_t)n0 * Cc, Cc, Cc / 64, sm, acc);

    const int seg = n0 / Dd, d0 = n0 % Dd;
#pragma unroll
    for (int mi = 0; mi < 4; mi++)
#pragma unroll
    for (int ni = 0; ni < 8; ni++)
#pragma unroll
    for (int h = 0; h < 2; h++){
        const int r   = wr * 64 + mi * 16 + (lane >> 2) + h * 8;
        const int col = wc * 64 + ni * 8 + (lane & 3) * 2;
        const int mrow = m0 + r;
        const int ng = n0 + col;
        const float v0 = acc[mi][ni][h * 2]     + g_bias[ng];
        const float v1 = acc[mi][ni][h * 2 + 1] + g_bias[ng + 1];
        const __half h0 = __float2half_rn(v0), h1 = __float2half_rn(v1);
        const int d = d0 + col;
        if (seg == 0){
            *(uint32_t*)(g_th + (size_t)mrow * Dd + d) = h2u2(h0, h1);
        } else if (seg == 1){
            *(uint32_t*)(g_ph + (size_t)mrow * Dd + d) = h2u2(h0, h1);
        } else {
            const int b = mrow >> 10, ml = mrow & 1023;
            g_gh[(size_t)(b * Dd + d)     * Nn + ml] = h0;
            g_gh[(size_t)(b * Dd + d + 1) * Nn + ml] = h1;
        }
    }
}

// ---------------- GEMM 2: scores = (theta @ phi^T) * adj ----------------
__global__ __launch_bounds__(128, 2) void k_score_t(const float* __restrict__ adj){
    extern __shared__ char sm[];
    const int lane = threadIdx.x & 31, w = threadIdx.x >> 5;
    const int wr = w >> 1, wc = w & 1;
    const int b = blockIdx.z, j0 = blockIdx.x * 128, i0 = blockIdx.y * 128;
    float acc[4][8][4];
    gemm1(g_th + (size_t)(b * Nn + i0) * Dd, Dd,
          g_ph + (size_t)(b * Nn + j0) * Dd, Dd, Dd / 64, sm, acc);

#pragma unroll
    for (int mi = 0; mi < 4; mi++)
#pragma unroll
    for (int ni = 0; ni < 8; ni++)
#pragma unroll
    for (int h = 0; h < 2; h++){
        const int i = i0 + wr * 64 + mi * 16 + (lane >> 2) + h * 8;
        const int j = j0 + wc * 64 + ni * 8 + (lane & 3) * 2;
        const size_t idx = ((size_t)b * Nn + i) * Nn + j;
        const float2 a2 = *(const float2*)(adj + idx);
        float2 o;
        o.x = acc[mi][ni][h * 2]     * a2.x;
        o.y = acc[mi][ni][h * 2 + 1] * a2.y;
        *(float2*)(g_attn + idx) = o;
    }
}

// ---------------- softmax -> plain fp16 rows ----------------
// 4 rows per 256-thread block; 64 threads per row; 4 float4 per thread (MLP=4).
__global__ __launch_bounds__(256) void k_softmax2(){
    const int slot = threadIdx.x >> 6;
    const int t    = threadIdx.x & 63;
    const size_t row = (size_t)blockIdx.x * 4 + slot;
    const float4* p = (const float4*)(g_attn + row * Nn);

    float4 v[4];
#pragma unroll
    for (int q = 0; q < 4; q++) v[q] = p[t + q * 64];

    float m = -1e30f;
#pragma unroll
    for (int q = 0; q < 4; q++)
        m = fmaxf(m, fmaxf(fmaxf(v[q].x, v[q].y), fmaxf(v[q].z, v[q].w)));
#pragma unroll
    for (int o = 16; o; o >>= 1) m = fmaxf(m, __shfl_xor_sync(0xffffffffu, m, o));
    __shared__ float red[8];
    const int wid = threadIdx.x >> 5;
    if ((threadIdx.x & 31) == 0) red[wid] = m;
    __syncthreads();
    const float bm = fmaxf(red[slot * 2], red[slot * 2 + 1]);
    __syncthreads();

    float s = 0.f;
#pragma unroll
    for (int q = 0; q < 4; q++){
        v[q].x = __expf(v[q].x - bm); v[q].y = __expf(v[q].y - bm);
        v[q].z = __expf(v[q].z - bm); v[q].w = __expf(v[q].w - bm);
        s += (v[q].x + v[q].y) + (v[q].z + v[q].w);
    }
#pragma unroll
    for (int o = 16; o; o >>= 1) s += __shfl_xor_sync(0xffffffffu, s, o);
    if ((threadIdx.x & 31) == 0) red[wid] = s;
    __syncthreads();
    const float inv = 1.0f / (red[slot * 2] + red[slot * 2 + 1]);

    __half* dst = g_ath + row * Nn;
#pragma unroll
    for (int q = 0; q < 4; q++){
        uint2 u;
        u.x = h2u2(__float2half_rn(v[q].x * inv), __float2half_rn(v[q].y * inv));
        u.y = h2u2(__float2half_rn(v[q].z * inv), __float2half_rn(v[q].w * inv));
        *(uint2*)(dst + (t + q * 64) * 4) = u;
    }
}

// ---------------- GEMM 3: attn @ g ----------------
__global__ __launch_bounds__(128, 2) void k_av_t(){
    extern __shared__ char sm[];
    const int lane = threadIdx.x & 31, w = threadIdx.x >> 5;
    const int wr = w >> 1, wc = w & 1;
    const int b = blockIdx.z, n0 = blockIdx.x * 128, i0 = blockIdx.y * 128;
    float acc[4][8][4];
    gemm1(g_ath + (size_t)(b * Nn + i0) * Nn, Nn,
          g_gh  + (size_t)(b * Dd + n0) * Nn, Nn, Nn / 64, sm, acc);

#pragma unroll
    for (int mi = 0; mi < 4; mi++)
#pragma unroll
    for (int ni = 0; ni < 8; ni++)
#pragma unroll
    for (int h = 0; h < 2; h++){
        const int r   = wr * 64 + mi * 16 + (lane >> 2) + h * 8;
        const int col = wc * 64 + ni * 8 + (lane & 3) * 2;
        const int mrow = b * Nn + i0 + r;
        const __half h0 = __float2half_rn(acc[mi][ni][h * 2]);
        const __half h1 = __float2half_rn(acc[mi][ni][h * 2 + 1]);
        *(uint32_t*)(g_odh + (size_t)mrow * Dd + n0 + col) = h2u2(h0, h1);
    }
}

// ---------------- GEMM 4: output + bias + residual ----------------
__global__ __launch_bounds__(128, 2) void k_out_t(
    const float* __restrict__ x, const float* __restrict__ bo, float* __restrict__ out)
{
    extern __shared__ char sm[];
    const int lane = threadIdx.x & 31, w = threadIdx.x >> 5;
    const int wr = w >> 1, wc = w & 1;
    const int n0 = blockIdx.x * 128, m0 = blockIdx.y * 128;
    float acc[4][8][4];
    gemm1(g_odh + (size_t)m0 * Dd, Dd,
          g_woh + (size_t)n0 * Dd, Dd, Dd / 64, sm, acc);

#pragma unroll
    for (int mi = 0; mi < 4; mi++)
#pragma unroll
    for (int ni = 0; ni < 8; ni++)
#pragma unroll
    for (int h = 0; h < 2; h++){
        const int row = m0 + wr * 64 + mi * 16 + (lane >> 2) + h * 8;
        const int cg  = n0 + wc * 64 + ni * 8 + (lane & 3) * 2;
        const size_t idx = (size_t)row * Cc + cg;
        const float2 xv = *(const float2*)(x + idx);
        const float2 bv = *(const float2*)(bo + cg);
        float2 o;
        o.x = acc[mi][ni][h * 2]     + bv.x + xv.x;
        o.y = acc[mi][ni][h * 2 + 1] + bv.y + xv.y;
        *(float2*)(out + idx) = o;
    }
}

// ---------------------------------------------------------------------------
extern "C" void kernel_launch(void* const* d_in, const int* in_sizes, int n_in,
                              void* d_out, int out_size)
{
    const float* x  = (const float*)d_in[0];
    const float* adj = (const float*)d_in[1];
    const float* Wt = (const float*)d_in[2];
    const float* bt = (const float*)d_in[3];
    const float* Wp = (const float*)d_in[4];
    const float* bp = (const float*)d_in[5];
    const float* Wg = (const float*)d_in[6];
    const float* bg = (const float*)d_in[7];
    const float* Wo = (const float*)d_in[8];
    const float* bo = (const float*)d_in[9];
    float* out = (float*)d_out;

    static bool attr_done = false;
    if (!attr_done){
        cudaFuncSetAttribute(k_proj_t,  cudaFuncAttributeMaxDynamicSharedMemorySize, SMEM_DYN);
        cudaFuncSetAttribute(k_score_t, cudaFuncAttributeMaxDynamicSharedMemorySize, SMEM_DYN);
        cudaFuncSetAttribute(k_av_t,    cudaFuncAttributeMaxDynamicSharedMemorySize, SMEM_DYN);
        cudaFuncSetAttribute(k_out_t,   cudaFuncAttributeMaxDynamicSharedMemorySize, SMEM_DYN);
        attr_done = true;
    }

    k_cvt_all<<<CVT_XB + CVT_WB + CVT_OB, 256>>>(x, Wt, bt, Wp, bp, Wg, bg, Wo);

    k_proj_t <<<dim3(9, 128),   128, SMEM_DYN>>>();
    k_score_t<<<dim3(8, 8, Bz), 128, SMEM_DYN>>>(adj);
    k_softmax2<<<(Bz * Nn) / 4, 256>>>();
    k_av_t   <<<dim3(3, 8, Bz), 128, SMEM_DYN>>>();
    k_out_t  <<<dim3(6, 128),   128, SMEM_DYN>>>(x, bo, out);
}